// round 2
// baseline (speedup 1.0000x reference)
#include <cuda_runtime.h>
#include <cuda_bf16.h>
#include <math.h>

#define NN 50000
#define EE 800000
#define ET (EE + NN)          // 850000 edges incl. self-loops
#define H1 4
#define C1 32
#define F1 128                // H1*C1
#define C2 64
#define NEG_SLOPE 0.2f

// ---------------- scratch (static device globals; no allocations) ----------
__device__ int   g_is64;
__device__ int   g_src [ET];
__device__ int   g_dst [ET];

__device__ float g_h1  [NN * F1];   // layer1 features (then reused for elu output)
__device__ float g_acc1[NN * F1];   // layer1 aggregation
__device__ float g_as1 [NN * H1];
__device__ float g_ad1 [NN * H1];
__device__ float g_emax1[NN * H1];
__device__ float g_den1 [NN * H1];
__device__ float g_e1  [ET * H1];

__device__ float g_h2  [NN * C2];
__device__ float g_as2 [NN];
__device__ float g_ad2 [NN];
__device__ float g_emax2[NN];
__device__ float g_den2 [NN];
__device__ float g_e2  [ET];

// ---------------- helpers ---------------------------------------------------
__device__ __forceinline__ void atomicMaxFloat(float* addr, float val) {
    if (val >= 0.0f) atomicMax((int*)addr, __float_as_int(val));
    else             atomicMin((unsigned int*)addr, __float_as_uint(val));
}

__device__ __forceinline__ float lrelu(float v) {
    return v > 0.0f ? v : NEG_SLOPE * v;
}

// ---------------- index dtype detection + conversion ------------------------
// If edge_index is int64, every 8-byte value is < NN (high word zero).
// If it is int32, an 8-byte read packs two indices; the high word is almost
// surely nonzero somewhere in the first 256 entries.
__global__ void detect_kernel(const void* __restrict__ ei) {
    if (threadIdx.x == 0) {
        const unsigned long long* p = (const unsigned long long*)ei;
        int ok = 1;
        for (int i = 0; i < 256; i++)
            if (p[i] >= (unsigned long long)NN) { ok = 0; break; }
        g_is64 = ok;
    }
}

__global__ void convert_kernel(const void* __restrict__ ei) {
    int e = blockIdx.x * blockDim.x + threadIdx.x;
    if (e >= ET) return;
    int s, d;
    if (e >= EE) {
        s = d = e - EE;                       // self-loop
    } else if (g_is64) {
        s = (int)((const long long*)ei)[e];
        d = (int)((const long long*)ei)[EE + e];
    } else {
        s = ((const int*)ei)[e];
        d = ((const int*)ei)[EE + e];
    }
    g_src[e] = s;
    g_dst[e] = d;
}

// ---------------- layer 1 ----------------------------------------------------
__global__ void init1_kernel() {
    int i = blockIdx.x * blockDim.x + threadIdx.x;
    if (i < NN * F1) g_acc1[i] = 0.0f;
    if (i < NN * H1) { g_emax1[i] = -INFINITY; g_den1[i] = 0.0f; }
}

// one block (128 thr) per node: h1 = x @ W1, plus per-head alpha reductions
__global__ void gemm1_kernel(const float* __restrict__ x,
                             const float* __restrict__ W1,
                             const float* __restrict__ att_s,
                             const float* __restrict__ att_d) {
    int n = blockIdx.x;
    int j = threadIdx.x;                 // 0..127 = head*32 + ch
    __shared__ float xs[128];
    xs[j] = x[n * 128 + j];
    __syncthreads();
    float acc = 0.0f;
#pragma unroll
    for (int k = 0; k < 128; k++) acc = fmaf(xs[k], W1[k * 128 + j], acc);
    g_h1[n * 128 + j] = acc;
    float vs = acc * att_s[j];
    float vd = acc * att_d[j];
#pragma unroll
    for (int o = 16; o; o >>= 1) {
        vs += __shfl_xor_sync(0xffffffffu, vs, o);
        vd += __shfl_xor_sync(0xffffffffu, vd, o);
    }
    if ((j & 31) == 0) {
        g_as1[n * H1 + (j >> 5)] = vs;
        g_ad1[n * H1 + (j >> 5)] = vd;
    }
}

__global__ void edge1a_kernel() {
    int gid = blockIdx.x * blockDim.x + threadIdx.x;
    if (gid >= ET * H1) return;
    int e = gid >> 2, h = gid & 3;
    int s = g_src[e], d = g_dst[e];
    float v = lrelu(g_as1[s * H1 + h] + g_ad1[d * H1 + h]);
    g_e1[gid] = v;
    atomicMaxFloat(&g_emax1[d * H1 + h], v);
}

__global__ void edge1b_kernel() {
    int gid = blockIdx.x * blockDim.x + threadIdx.x;
    if (gid >= ET * H1) return;
    int e = gid >> 2, h = gid & 3;
    int d = g_dst[e];
    float ex = expf(g_e1[gid] - g_emax1[d * H1 + h]);
    g_e1[gid] = ex;
    atomicAdd(&g_den1[d * H1 + h], ex);
}

__global__ void edge1c_kernel() {
    long long gid = (long long)blockIdx.x * blockDim.x + threadIdx.x;
    if (gid >= (long long)ET * 32) return;   // 32 thr/edge, 4 ch each
    int e = (int)(gid >> 5);
    int q = (int)(gid & 31);
    int j = q << 2;                          // channel base 0..124
    int h = j >> 5;
    int s = g_src[e], d = g_dst[e];
    float coef = g_e1[e * H1 + h] / (g_den1[d * H1 + h] + 1e-16f);
    float4 hv = *(const float4*)&g_h1[s * 128 + j];
    float* o = &g_acc1[d * 128 + j];
    atomicAdd(o + 0, hv.x * coef);
    atomicAdd(o + 1, hv.y * coef);
    atomicAdd(o + 2, hv.z * coef);
    atomicAdd(o + 3, hv.w * coef);
}

// elu(acc + b1) -> back into g_h1 (reuse)
__global__ void elu1_kernel(const float* __restrict__ b1) {
    int i = blockIdx.x * blockDim.x + threadIdx.x;
    if (i >= NN * F1) return;
    float v = g_acc1[i] + b1[i & 127];
    g_h1[i] = v > 0.0f ? v : expm1f(v);
}

// ---------------- layer 2 ----------------------------------------------------
__global__ void init2_kernel(float* __restrict__ out, const float* __restrict__ b2) {
    int i = blockIdx.x * blockDim.x + threadIdx.x;
    if (i < NN * C2) out[i] = b2[i & 63];
    if (i < NN) { g_emax2[i] = -INFINITY; g_den2[i] = 0.0f; }
}

// one block (64 thr) per node: h2 = h1e @ W2, plus alpha reductions over 64 ch
__global__ void gemm2_kernel(const float* __restrict__ W2,
                             const float* __restrict__ att_s,
                             const float* __restrict__ att_d) {
    int n = blockIdx.x;
    int j = threadIdx.x;                 // 0..63
    __shared__ float xs[128];
    xs[j]      = g_h1[n * 128 + j];
    xs[j + 64] = g_h1[n * 128 + j + 64];
    __syncthreads();
    float acc = 0.0f;
#pragma unroll
    for (int k = 0; k < 128; k++) acc = fmaf(xs[k], W2[k * 64 + j], acc);
    g_h2[n * 64 + j] = acc;
    float vs = acc * att_s[j];
    float vd = acc * att_d[j];
#pragma unroll
    for (int o = 16; o; o >>= 1) {
        vs += __shfl_xor_sync(0xffffffffu, vs, o);
        vd += __shfl_xor_sync(0xffffffffu, vd, o);
    }
    __shared__ float ps[2], pd[2];
    if ((j & 31) == 0) { ps[j >> 5] = vs; pd[j >> 5] = vd; }
    __syncthreads();
    if (j == 0) { g_as2[n] = ps[0] + ps[1]; g_ad2[n] = pd[0] + pd[1]; }
}

__global__ void edge2a_kernel() {
    int e = blockIdx.x * blockDim.x + threadIdx.x;
    if (e >= ET) return;
    int s = g_src[e], d = g_dst[e];
    float v = lrelu(g_as2[s] + g_ad2[d]);
    g_e2[e] = v;
    atomicMaxFloat(&g_emax2[d], v);
}

__global__ void edge2b_kernel() {
    int e = blockIdx.x * blockDim.x + threadIdx.x;
    if (e >= ET) return;
    int d = g_dst[e];
    float ex = expf(g_e2[e] - g_emax2[d]);
    g_e2[e] = ex;
    atomicAdd(&g_den2[d], ex);
}

__global__ void edge2c_kernel(float* __restrict__ out) {
    long long gid = (long long)blockIdx.x * blockDim.x + threadIdx.x;
    if (gid >= (long long)ET * 16) return;   // 16 thr/edge, 4 ch each
    int e = (int)(gid >> 4);
    int j = (int)(gid & 15) << 2;            // channel base 0..60
    int s = g_src[e], d = g_dst[e];
    float coef = g_e2[e] / (g_den2[d] + 1e-16f);
    float4 hv = *(const float4*)&g_h2[s * 64 + j];
    float* o = &out[d * 64 + j];
    atomicAdd(o + 0, hv.x * coef);
    atomicAdd(o + 1, hv.y * coef);
    atomicAdd(o + 2, hv.z * coef);
    atomicAdd(o + 3, hv.w * coef);
}

// ---------------- launch -----------------------------------------------------
extern "C" void kernel_launch(void* const* d_in, const int* in_sizes, int n_in,
                              void* d_out, int out_size) {
    const float*     x    = (const float*)d_in[0];
    const void*      ei   = d_in[1];
    const float*     W1   = (const float*)d_in[2];
    const float*     as1  = (const float*)d_in[3];
    const float*     ad1  = (const float*)d_in[4];
    const float*     b1   = (const float*)d_in[5];
    const float*     W2   = (const float*)d_in[6];
    const float*     as2  = (const float*)d_in[7];
    const float*     ad2  = (const float*)d_in[8];
    const float*     b2   = (const float*)d_in[9];
    float*           out  = (float*)d_out;

    const int TB = 256;
    auto nb = [](long long n, int tb) { return (int)((n + tb - 1) / tb); };

    // index prep
    detect_kernel<<<1, 32>>>(ei);
    convert_kernel<<<nb(ET, TB), TB>>>(ei);

    // layer 1
    init1_kernel<<<nb((long long)NN * F1, TB), TB>>>();
    gemm1_kernel<<<NN, 128>>>(x, W1, as1, ad1);
    edge1a_kernel<<<nb((long long)ET * H1, TB), TB>>>();
    edge1b_kernel<<<nb((long long)ET * H1, TB), TB>>>();
    edge1c_kernel<<<nb((long long)ET * 32, TB), TB>>>();
    elu1_kernel<<<nb((long long)NN * F1, TB), TB>>>(b1);

    // layer 2
    init2_kernel<<<nb((long long)NN * C2, TB), TB>>>(out, b2);
    gemm2_kernel<<<NN, 64>>>(W2, as2, ad2);
    edge2a_kernel<<<nb((long long)ET, TB), TB>>>();
    edge2b_kernel<<<nb((long long)ET, TB), TB>>>();
    edge2c_kernel<<<nb((long long)ET * 16, TB), TB>>>(out);
}

// round 3
// speedup vs baseline: 1.8251x; 1.8251x over previous
#include <cuda_runtime.h>
#include <cuda_bf16.h>
#include <math.h>

#define NN 50000
#define EE 800000
#define ET (EE + NN)          // edges incl. self-loops
#define F1 128
#define C2 64
#define NEG 0.2f
#define MINIT -1e30f

// ---------------- scratch ----------------------------------------------------
__device__ int    g_is64;
__device__ int    g_src [ET];
__device__ int    g_dst [ET];
__device__ int    g_row [NN + 1];
__device__ int    g_wpos[NN];
__device__ int    g_csrc[ET];
__device__ int    g_cdst[ET];
__device__ float4 g_c1  [ET];
__device__ float  g_c2  [ET];

__device__ float  g_h1  [NN * F1];
__device__ float  g_h1e [NN * F1];
__device__ float4 g_as1 [NN];
__device__ float4 g_ad1 [NN];
__device__ float4 g_m1  [NN];
__device__ float4 g_inv1[NN];

__device__ float  g_h2  [NN * C2];
__device__ float  g_as2 [NN];
__device__ float  g_ad2 [NN];
__device__ float  g_m2  [NN];
__device__ float  g_inv2[NN];

__device__ __forceinline__ float lrelu(float v) { return v > 0.0f ? v : NEG * v; }

// ---------------- index prep -------------------------------------------------
__global__ void detect_kernel(const void* __restrict__ ei) {
    if (threadIdx.x == 0) {
        const unsigned long long* p = (const unsigned long long*)ei;
        int ok = 1;
        for (int i = 0; i < 256; i++)
            if (p[i] >= (unsigned long long)NN) { ok = 0; break; }
        g_is64 = ok;
    }
}

__global__ void convert_kernel(const void* __restrict__ ei) {
    int e = blockIdx.x * blockDim.x + threadIdx.x;
    if (e >= ET) return;
    int s, d;
    if (e >= EE) s = d = e - EE;
    else if (g_is64) {
        s = (int)((const long long*)ei)[e];
        d = (int)((const long long*)ei)[EE + e];
    } else {
        s = ((const int*)ei)[e];
        d = ((const int*)ei)[EE + e];
    }
    g_src[e] = s;
    g_dst[e] = d;
}

// ---------------- CSR build --------------------------------------------------
__global__ void zero_cnt_kernel() {
    int i = blockIdx.x * blockDim.x + threadIdx.x;
    if (i < NN) g_wpos[i] = 0;
}

__global__ void hist_kernel() {
    int e = blockIdx.x * blockDim.x + threadIdx.x;
    if (e < ET) atomicAdd(&g_wpos[g_dst[e]], 1);
}

__global__ void scan_kernel() {        // single block, 1024 threads
    __shared__ int ssum[1024];
    int t = threadIdx.x;
    const int CH = (NN + 1023) / 1024;
    int lo = t * CH, hi = min(lo + CH, NN);
    int s = 0;
    for (int i = lo; i < hi; i++) s += g_wpos[i];
    ssum[t] = s;
    __syncthreads();
    for (int o = 1; o < 1024; o <<= 1) {
        int v = (t >= o) ? ssum[t - o] : 0;
        __syncthreads();
        ssum[t] += v;
        __syncthreads();
    }
    int run = (t > 0) ? ssum[t - 1] : 0;
    for (int i = lo; i < hi; i++) {
        int c = g_wpos[i];
        g_row[i] = run;
        run += c;
    }
    if (t == 1023) g_row[NN] = ET;
    __syncthreads();
    for (int i = lo; i < hi; i++) g_wpos[i] = g_row[i];
}

__global__ void scatter_kernel() {
    int e = blockIdx.x * blockDim.x + threadIdx.x;
    if (e >= ET) return;
    int d = g_dst[e];
    int p = atomicAdd(&g_wpos[d], 1);
    g_csrc[p] = g_src[e];
    g_cdst[p] = d;
}

// ---------------- gemm1: h1 = x@W1, alpha reductions --------------------------
// 128 threads, 8 nodes per block. thread = output column.
__global__ void gemm1_kernel(const float* __restrict__ x,
                             const float* __restrict__ W,
                             const float* __restrict__ as,
                             const float* __restrict__ ad) {
    __shared__ float xs[8][128];
    int n0 = blockIdx.x * 8;
    int t = threadIdx.x;
    const float4* x4 = (const float4*)(x + n0 * 128);
    float4* xs4 = (float4*)xs;
    xs4[t] = x4[t];
    xs4[t + 128] = x4[t + 128];
    __syncthreads();
    int j = t;
    float acc[8] = {0, 0, 0, 0, 0, 0, 0, 0};
#pragma unroll
    for (int k = 0; k < 128; k += 4) {
        float w0 = W[(k + 0) * 128 + j];
        float w1 = W[(k + 1) * 128 + j];
        float w2 = W[(k + 2) * 128 + j];
        float w3 = W[(k + 3) * 128 + j];
#pragma unroll
        for (int n = 0; n < 8; n++) {
            float4 xv = *(const float4*)&xs[n][k];
            acc[n] = fmaf(xv.x, w0, acc[n]);
            acc[n] = fmaf(xv.y, w1, acc[n]);
            acc[n] = fmaf(xv.z, w2, acc[n]);
            acc[n] = fmaf(xv.w, w3, acc[n]);
        }
    }
    float asj = as[j], adj = ad[j];
    int h = j >> 5;
#pragma unroll
    for (int n = 0; n < 8; n++) {
        g_h1[(n0 + n) * 128 + j] = acc[n];
        float vs = acc[n] * asj;
        float vd = acc[n] * adj;
#pragma unroll
        for (int o = 16; o; o >>= 1) {
            vs += __shfl_xor_sync(0xffffffffu, vs, o);
            vd += __shfl_xor_sync(0xffffffffu, vd, o);
        }
        if ((j & 31) == 0) {
            ((float*)&g_as1[n0 + n])[h] = vs;
            ((float*)&g_ad1[n0 + n])[h] = vd;
        }
    }
}

// ---------------- softmax stats layer1: warp per node -------------------------
__device__ __forceinline__ void online_upd(float& m, float& s, float e) {
    float mn = fmaxf(m, e);
    s = s * __expf(m - mn) + __expf(e - mn);
    m = mn;
}

__global__ void sm1_kernel() {
    int warp = threadIdx.x >> 5, lane = threadIdx.x & 31;
    int d = blockIdx.x * 8 + warp;
    int lo = g_row[d], hi = g_row[d + 1];
    float4 ad = g_ad1[d];
    float m0 = MINIT, m1 = MINIT, m2 = MINIT, m3 = MINIT;
    float s0 = 0, s1 = 0, s2 = 0, s3 = 0;
    for (int i = lo + lane; i < hi; i += 32) {
        int sc = g_csrc[i];
        float4 a = g_as1[sc];
        online_upd(m0, s0, lrelu(a.x + ad.x));
        online_upd(m1, s1, lrelu(a.y + ad.y));
        online_upd(m2, s2, lrelu(a.z + ad.z));
        online_upd(m3, s3, lrelu(a.w + ad.w));
    }
#pragma unroll
    for (int o = 16; o; o >>= 1) {
        float mo, so, mn;
        mo = __shfl_xor_sync(0xffffffffu, m0, o); so = __shfl_xor_sync(0xffffffffu, s0, o);
        mn = fmaxf(m0, mo); s0 = s0 * __expf(m0 - mn) + so * __expf(mo - mn); m0 = mn;
        mo = __shfl_xor_sync(0xffffffffu, m1, o); so = __shfl_xor_sync(0xffffffffu, s1, o);
        mn = fmaxf(m1, mo); s1 = s1 * __expf(m1 - mn) + so * __expf(mo - mn); m1 = mn;
        mo = __shfl_xor_sync(0xffffffffu, m2, o); so = __shfl_xor_sync(0xffffffffu, s2, o);
        mn = fmaxf(m2, mo); s2 = s2 * __expf(m2 - mn) + so * __expf(mo - mn); m2 = mn;
        mo = __shfl_xor_sync(0xffffffffu, m3, o); so = __shfl_xor_sync(0xffffffffu, s3, o);
        mn = fmaxf(m3, mo); s3 = s3 * __expf(m3 - mn) + so * __expf(mo - mn); m3 = mn;
    }
    if (lane == 0) {
        g_m1[d] = make_float4(m0, m1, m2, m3);
        g_inv1[d] = make_float4(1.0f / (s0 + 1e-16f), 1.0f / (s1 + 1e-16f),
                                1.0f / (s2 + 1e-16f), 1.0f / (s3 + 1e-16f));
    }
}

__global__ void coef1_kernel() {
    int i = blockIdx.x * blockDim.x + threadIdx.x;
    if (i >= ET) return;
    int s = g_csrc[i], d = g_cdst[i];
    float4 a = g_as1[s], b = g_ad1[d], m = g_m1[d], v = g_inv1[d];
    float4 c;
    c.x = __expf(lrelu(a.x + b.x) - m.x) * v.x;
    c.y = __expf(lrelu(a.y + b.y) - m.y) * v.y;
    c.z = __expf(lrelu(a.z + b.z) - m.z) * v.z;
    c.w = __expf(lrelu(a.w + b.w) - m.w) * v.w;
    g_c1[i] = c;
}

// ---------------- agg1: block(128) per node; out = elu(sum + b1) -------------
__global__ void agg1_kernel(const float* __restrict__ b1) {
    int d = blockIdx.x;
    int j = threadIdx.x;
    int lo = g_row[d], hi = g_row[d + 1];
    int h = j >> 5;
    const float* c1f = (const float*)g_c1;
    float acc = 0.0f;
    int i = lo;
    for (; i + 4 <= hi; i += 4) {
        int s0 = g_csrc[i], s1 = g_csrc[i + 1], s2 = g_csrc[i + 2], s3 = g_csrc[i + 3];
        float c0 = c1f[(i + 0) * 4 + h];
        float c1 = c1f[(i + 1) * 4 + h];
        float c2 = c1f[(i + 2) * 4 + h];
        float c3 = c1f[(i + 3) * 4 + h];
        float v0 = g_h1[s0 * 128 + j];
        float v1 = g_h1[s1 * 128 + j];
        float v2 = g_h1[s2 * 128 + j];
        float v3 = g_h1[s3 * 128 + j];
        acc = fmaf(c0, v0, acc);
        acc = fmaf(c1, v1, acc);
        acc = fmaf(c2, v2, acc);
        acc = fmaf(c3, v3, acc);
    }
    for (; i < hi; i++) {
        int s = g_csrc[i];
        acc = fmaf(c1f[i * 4 + h], g_h1[s * 128 + j], acc);
    }
    float r = acc + b1[j];
    g_h1e[d * 128 + j] = r > 0.0f ? r : expm1f(r);
}

// ---------------- gemm2 --------------------------------------------------------
__global__ void gemm2_kernel(const float* __restrict__ W,
                             const float* __restrict__ as,
                             const float* __restrict__ ad) {
    __shared__ float xs[8][128];
    __shared__ float ps[8][2], pd[8][2];
    int n0 = blockIdx.x * 8;
    int t = threadIdx.x;   // 64
    const float4* x4 = (const float4*)(g_h1e + n0 * 128);
    float4* xs4 = (float4*)xs;
    xs4[t] = x4[t];
    xs4[t + 64] = x4[t + 64];
    xs4[t + 128] = x4[t + 128];
    xs4[t + 192] = x4[t + 192];
    __syncthreads();
    int j = t;
    float acc[8] = {0, 0, 0, 0, 0, 0, 0, 0};
#pragma unroll
    for (int k = 0; k < 128; k += 4) {
        float w0 = W[(k + 0) * 64 + j];
        float w1 = W[(k + 1) * 64 + j];
        float w2 = W[(k + 2) * 64 + j];
        float w3 = W[(k + 3) * 64 + j];
#pragma unroll
        for (int n = 0; n < 8; n++) {
            float4 xv = *(const float4*)&xs[n][k];
            acc[n] = fmaf(xv.x, w0, acc[n]);
            acc[n] = fmaf(xv.y, w1, acc[n]);
            acc[n] = fmaf(xv.z, w2, acc[n]);
            acc[n] = fmaf(xv.w, w3, acc[n]);
        }
    }
    float asj = as[j], adj = ad[j];
    int w = t >> 5;
#pragma unroll
    for (int n = 0; n < 8; n++) {
        g_h2[(n0 + n) * 64 + j] = acc[n];
        float vs = acc[n] * asj;
        float vd = acc[n] * adj;
#pragma unroll
        for (int o = 16; o; o >>= 1) {
            vs += __shfl_xor_sync(0xffffffffu, vs, o);
            vd += __shfl_xor_sync(0xffffffffu, vd, o);
        }
        if ((t & 31) == 0) { ps[n][w] = vs; pd[n][w] = vd; }
    }
    __syncthreads();
    if (t < 8) {
        g_as2[n0 + t] = ps[t][0] + ps[t][1];
        g_ad2[n0 + t] = pd[t][0] + pd[t][1];
    }
}

__global__ void sm2_kernel() {
    int warp = threadIdx.x >> 5, lane = threadIdx.x & 31;
    int d = blockIdx.x * 8 + warp;
    int lo = g_row[d], hi = g_row[d + 1];
    float add = g_ad2[d];
    float m = MINIT, s = 0.0f;
    for (int i = lo + lane; i < hi; i += 32) {
        int sc = g_csrc[i];
        online_upd(m, s, lrelu(g_as2[sc] + add));
    }
#pragma unroll
    for (int o = 16; o; o >>= 1) {
        float mo = __shfl_xor_sync(0xffffffffu, m, o);
        float so = __shfl_xor_sync(0xffffffffu, s, o);
        float mn = fmaxf(m, mo);
        s = s * __expf(m - mn) + so * __expf(mo - mn);
        m = mn;
    }
    if (lane == 0) {
        g_m2[d] = m;
        g_inv2[d] = 1.0f / (s + 1e-16f);
    }
}

__global__ void coef2_kernel() {
    int i = blockIdx.x * blockDim.x + threadIdx.x;
    if (i >= ET) return;
    int s = g_csrc[i], d = g_cdst[i];
    g_c2[i] = __expf(lrelu(g_as2[s] + g_ad2[d]) - g_m2[d]) * g_inv2[d];
}

// ---------------- agg2: block(64) per node -> out -----------------------------
__global__ void agg2_kernel(float* __restrict__ out, const float* __restrict__ b2) {
    int d = blockIdx.x;
    int j = threadIdx.x;
    int lo = g_row[d], hi = g_row[d + 1];
    float acc = 0.0f;
    int i = lo;
    for (; i + 4 <= hi; i += 4) {
        int s0 = g_csrc[i], s1 = g_csrc[i + 1], s2 = g_csrc[i + 2], s3 = g_csrc[i + 3];
        float c0 = g_c2[i + 0], c1 = g_c2[i + 1], c2 = g_c2[i + 2], c3 = g_c2[i + 3];
        float v0 = g_h2[s0 * 64 + j];
        float v1 = g_h2[s1 * 64 + j];
        float v2 = g_h2[s2 * 64 + j];
        float v3 = g_h2[s3 * 64 + j];
        acc = fmaf(c0, v0, acc);
        acc = fmaf(c1, v1, acc);
        acc = fmaf(c2, v2, acc);
        acc = fmaf(c3, v3, acc);
    }
    for (; i < hi; i++) acc = fmaf(g_c2[i], g_h2[g_csrc[i] * 64 + j], acc);
    out[d * 64 + j] = acc + b2[j];
}

// ---------------- launch -------------------------------------------------------
extern "C" void kernel_launch(void* const* d_in, const int* in_sizes, int n_in,
                              void* d_out, int out_size) {
    const float* x   = (const float*)d_in[0];
    const void*  ei  = d_in[1];
    const float* W1  = (const float*)d_in[2];
    const float* as1 = (const float*)d_in[3];
    const float* ad1 = (const float*)d_in[4];
    const float* b1  = (const float*)d_in[5];
    const float* W2  = (const float*)d_in[6];
    const float* as2 = (const float*)d_in[7];
    const float* ad2 = (const float*)d_in[8];
    const float* b2  = (const float*)d_in[9];
    float*       out = (float*)d_out;

    const int TB = 256;
    auto nb = [](long long n, int tb) { return (int)((n + tb - 1) / tb); };

    detect_kernel<<<1, 32>>>(ei);
    convert_kernel<<<nb(ET, TB), TB>>>(ei);

    zero_cnt_kernel<<<nb(NN, TB), TB>>>();
    hist_kernel<<<nb(ET, TB), TB>>>();
    scan_kernel<<<1, 1024>>>();
    scatter_kernel<<<nb(ET, TB), TB>>>();

    gemm1_kernel<<<NN / 8, 128>>>(x, W1, as1, ad1);
    sm1_kernel<<<NN / 8, 256>>>();
    coef1_kernel<<<nb(ET, TB), TB>>>();
    agg1_kernel<<<NN, 128>>>(b1);

    gemm2_kernel<<<NN / 8, 64>>>(W2, as2, ad2);
    sm2_kernel<<<NN / 8, 256>>>();
    coef2_kernel<<<nb(ET, TB), TB>>>();
    agg2_kernel<<<NN, 64>>>(out, b2);
}

// round 4
// speedup vs baseline: 2.2402x; 1.2275x over previous
#include <cuda_runtime.h>
#include <cuda_bf16.h>
#include <math.h>

#define NN 50000
#define EE 800000
#define ET (EE + NN)
#define F1 128
#define C2 64
#define NEG 0.2f
#define MINIT -1e30f

// ---------------- scratch ----------------------------------------------------
__device__ int    g_is64;
__device__ int    g_src [ET];
__device__ int    g_dst [ET];
__device__ int    g_row [NN + 1];
__device__ int    g_wpos[NN];
__device__ int    g_csrc[ET];

__device__ float  g_h1  [NN * F1];
__device__ float  g_h1e [NN * F1];
__device__ float4 g_as1 [NN];
__device__ float4 g_ad1 [NN];

__device__ float  g_h2  [NN * C2];
__device__ float  g_as2 [NN];
__device__ float  g_ad2 [NN];

__device__ __forceinline__ float lrelu(float v) { return v > 0.0f ? v : NEG * v; }

// ---------------- index prep + CSR build -------------------------------------
__global__ void detect_kernel(const void* __restrict__ ei) {
    if (threadIdx.x == 0) {
        const unsigned long long* p = (const unsigned long long*)ei;
        int ok = 1;
        for (int i = 0; i < 256; i++)
            if (p[i] >= (unsigned long long)NN) { ok = 0; break; }
        g_is64 = ok;
    }
}

__global__ void zero_cnt_kernel() {
    int i = blockIdx.x * blockDim.x + threadIdx.x;
    if (i < NN) g_wpos[i] = 0;
}

__global__ void convert_hist_kernel(const void* __restrict__ ei) {
    int e = blockIdx.x * blockDim.x + threadIdx.x;
    if (e >= ET) return;
    int s, d;
    if (e >= EE) s = d = e - EE;
    else if (g_is64) {
        s = (int)((const long long*)ei)[e];
        d = (int)((const long long*)ei)[EE + e];
    } else {
        s = ((const int*)ei)[e];
        d = ((const int*)ei)[EE + e];
    }
    g_src[e] = s;
    g_dst[e] = d;
    atomicAdd(&g_wpos[d], 1);
}

__global__ void scan_kernel() {        // single block, 1024 threads
    __shared__ int ssum[1024];
    int t = threadIdx.x;
    const int CH = (NN + 1023) / 1024;
    int lo = t * CH, hi = min(lo + CH, NN);
    int s = 0;
    for (int i = lo; i < hi; i++) s += g_wpos[i];
    ssum[t] = s;
    __syncthreads();
    for (int o = 1; o < 1024; o <<= 1) {
        int v = (t >= o) ? ssum[t - o] : 0;
        __syncthreads();
        ssum[t] += v;
        __syncthreads();
    }
    int run = (t > 0) ? ssum[t - 1] : 0;
    for (int i = lo; i < hi; i++) {
        int c = g_wpos[i];
        g_row[i] = run;
        run += c;
    }
    if (t == 1023) g_row[NN] = ET;
    __syncthreads();
    for (int i = lo; i < hi; i++) g_wpos[i] = g_row[i];
}

__global__ void scatter_kernel() {
    int e = blockIdx.x * blockDim.x + threadIdx.x;
    if (e >= ET) return;
    int d = g_dst[e];
    int p = atomicAdd(&g_wpos[d], 1);
    g_csrc[p] = g_src[e];
}

// ---------------- gemm1: h1 = x@W1 + alpha reductions (16 nodes/block) -------
__global__ void __launch_bounds__(128) gemm1_kernel(
        const float* __restrict__ x, const float* __restrict__ W,
        const float* __restrict__ as, const float* __restrict__ ad) {
    __shared__ float xs[16][128];
    int n0 = blockIdx.x * 16;
    int t = threadIdx.x;
    const float4* x4 = (const float4*)(x + n0 * 128);
    float4* xs4 = (float4*)xs;
#pragma unroll
    for (int r = 0; r < 4; r++) xs4[t + r * 128] = x4[t + r * 128];
    __syncthreads();
    int j = t;
    float acc[16];
#pragma unroll
    for (int n = 0; n < 16; n++) acc[n] = 0.0f;
#pragma unroll
    for (int k = 0; k < 128; k += 4) {
        float w0 = W[(k + 0) * 128 + j];
        float w1 = W[(k + 1) * 128 + j];
        float w2 = W[(k + 2) * 128 + j];
        float w3 = W[(k + 3) * 128 + j];
#pragma unroll
        for (int n = 0; n < 16; n++) {
            float4 xv = *(const float4*)&xs[n][k];
            acc[n] = fmaf(xv.x, w0, acc[n]);
            acc[n] = fmaf(xv.y, w1, acc[n]);
            acc[n] = fmaf(xv.z, w2, acc[n]);
            acc[n] = fmaf(xv.w, w3, acc[n]);
        }
    }
    float asj = as[j], adj = ad[j];
    int h = j >> 5;
#pragma unroll
    for (int n = 0; n < 16; n++) {
        g_h1[(n0 + n) * 128 + j] = acc[n];
        float vs = acc[n] * asj;
        float vd = acc[n] * adj;
#pragma unroll
        for (int o = 16; o; o >>= 1) {
            vs += __shfl_xor_sync(0xffffffffu, vs, o);
            vd += __shfl_xor_sync(0xffffffffu, vd, o);
        }
        if ((j & 31) == 0) {
            ((float*)&g_as1[n0 + n])[h] = vs;
            ((float*)&g_ad1[n0 + n])[h] = vd;
        }
    }
}

// ---------------- fused online-softmax aggregation, layer 1 -------------------
// warp per dst node; lane handles 4 channels (one head per 8-lane group).
__global__ void __launch_bounds__(256) agg1_kernel(const float* __restrict__ b1) {
    int warp = threadIdx.x >> 5, lane = threadIdx.x & 31;
    int d = blockIdx.x * 8 + warp;
    int lo = g_row[d], hi = g_row[d + 1];
    int h = lane >> 3;                       // head for this lane's channels
    float add = ((const float*)&g_ad1[d])[h];
    float m = MINIT, s = 0.0f;
    float4 acc = make_float4(0, 0, 0, 0);
    for (int i = lo; i < hi; i++) {
        int sc = g_csrc[i];
        float e = lrelu(((const float*)&g_as1[sc])[h] + add);
        float4 hv = *(const float4*)&g_h1[sc * 128 + lane * 4];
        float mn = fmaxf(m, e);
        float r = __expf(m - mn);            // 1 when max unchanged
        float w = __expf(e - mn);
        s = s * r + w;
        acc.x = fmaf(acc.x, r, w * hv.x);
        acc.y = fmaf(acc.y, r, w * hv.y);
        acc.z = fmaf(acc.z, r, w * hv.z);
        acc.w = fmaf(acc.w, r, w * hv.w);
        m = mn;
    }
    float inv = 1.0f / (s + 1e-16f);
    int j = lane * 4;
    float4 bv = *(const float4*)&b1[j];
    float4 o;
    o.x = acc.x * inv + bv.x;
    o.y = acc.y * inv + bv.y;
    o.z = acc.z * inv + bv.z;
    o.w = acc.w * inv + bv.w;
    o.x = o.x > 0.0f ? o.x : expm1f(o.x);
    o.y = o.y > 0.0f ? o.y : expm1f(o.y);
    o.z = o.z > 0.0f ? o.z : expm1f(o.z);
    o.w = o.w > 0.0f ? o.w : expm1f(o.w);
    *(float4*)&g_h1e[d * 128 + j] = o;
}

// ---------------- gemm2 (16 nodes/block, 64 threads) --------------------------
__global__ void __launch_bounds__(64) gemm2_kernel(
        const float* __restrict__ W,
        const float* __restrict__ as, const float* __restrict__ ad) {
    __shared__ float xs[16][128];
    __shared__ float ps[16][2], pd[16][2];
    int n0 = blockIdx.x * 16;
    int t = threadIdx.x;                     // 0..63
    const float4* x4 = (const float4*)(g_h1e + n0 * 128);
    float4* xs4 = (float4*)xs;
#pragma unroll
    for (int r = 0; r < 8; r++) xs4[t + r * 64] = x4[t + r * 64];
    __syncthreads();
    int j = t;
    float acc[16];
#pragma unroll
    for (int n = 0; n < 16; n++) acc[n] = 0.0f;
#pragma unroll
    for (int k = 0; k < 128; k += 4) {
        float w0 = W[(k + 0) * 64 + j];
        float w1 = W[(k + 1) * 64 + j];
        float w2 = W[(k + 2) * 64 + j];
        float w3 = W[(k + 3) * 64 + j];
#pragma unroll
        for (int n = 0; n < 16; n++) {
            float4 xv = *(const float4*)&xs[n][k];
            acc[n] = fmaf(xv.x, w0, acc[n]);
            acc[n] = fmaf(xv.y, w1, acc[n]);
            acc[n] = fmaf(xv.z, w2, acc[n]);
            acc[n] = fmaf(xv.w, w3, acc[n]);
        }
    }
    float asj = as[j], adj = ad[j];
    int w = t >> 5;
#pragma unroll
    for (int n = 0; n < 16; n++) {
        g_h2[(n0 + n) * 64 + j] = acc[n];
        float vs = acc[n] * asj;
        float vd = acc[n] * adj;
#pragma unroll
        for (int o = 16; o; o >>= 1) {
            vs += __shfl_xor_sync(0xffffffffu, vs, o);
            vd += __shfl_xor_sync(0xffffffffu, vd, o);
        }
        if ((t & 31) == 0) { ps[n][w] = vs; pd[n][w] = vd; }
    }
    __syncthreads();
    if (t < 16) {
        g_as2[n0 + t] = ps[t][0] + ps[t][1];
        g_ad2[n0 + t] = pd[t][0] + pd[t][1];
    }
}

// ---------------- fused online-softmax aggregation, layer 2 -------------------
// warp per dst node; lane handles 2 channels.
__global__ void __launch_bounds__(256) agg2_kernel(
        float* __restrict__ out, const float* __restrict__ b2) {
    int warp = threadIdx.x >> 5, lane = threadIdx.x & 31;
    int d = blockIdx.x * 8 + warp;
    int lo = g_row[d], hi = g_row[d + 1];
    float add = g_ad2[d];
    float m = MINIT, s = 0.0f;
    float2 acc = make_float2(0, 0);
    for (int i = lo; i < hi; i++) {
        int sc = g_csrc[i];
        float e = lrelu(g_as2[sc] + add);
        float2 hv = *(const float2*)&g_h2[sc * 64 + lane * 2];
        float mn = fmaxf(m, e);
        float r = __expf(m - mn);
        float w = __expf(e - mn);
        s = s * r + w;
        acc.x = fmaf(acc.x, r, w * hv.x);
        acc.y = fmaf(acc.y, r, w * hv.y);
        m = mn;
    }
    float inv = 1.0f / (s + 1e-16f);
    int j = lane * 2;
    float2 o;
    o.x = acc.x * inv + b2[j];
    o.y = acc.y * inv + b2[j + 1];
    *(float2*)&out[d * 64 + j] = o;
}

// ---------------- launch -------------------------------------------------------
extern "C" void kernel_launch(void* const* d_in, const int* in_sizes, int n_in,
                              void* d_out, int out_size) {
    const float* x   = (const float*)d_in[0];
    const void*  ei  = d_in[1];
    const float* W1  = (const float*)d_in[2];
    const float* as1 = (const float*)d_in[3];
    const float* ad1 = (const float*)d_in[4];
    const float* b1  = (const float*)d_in[5];
    const float* W2  = (const float*)d_in[6];
    const float* as2 = (const float*)d_in[7];
    const float* ad2 = (const float*)d_in[8];
    const float* b2  = (const float*)d_in[9];
    float*       out = (float*)d_out;

    const int TB = 256;
    auto nb = [](long long n, int tb) { return (int)((n + tb - 1) / tb); };

    detect_kernel<<<1, 32>>>(ei);
    zero_cnt_kernel<<<nb(NN, TB), TB>>>();
    convert_hist_kernel<<<nb(ET, TB), TB>>>(ei);
    scan_kernel<<<1, 1024>>>();
    scatter_kernel<<<nb(ET, TB), TB>>>();

    gemm1_kernel<<<NN / 16, 128>>>(x, W1, as1, ad1);
    agg1_kernel<<<NN / 8, 256>>>(b1);

    gemm2_kernel<<<NN / 16, 64>>>(W2, as2, ad2);
    agg2_kernel<<<NN / 8, 256>>>(out, b2);
}

// round 5
// speedup vs baseline: 3.0301x; 1.3526x over previous
#include <cuda_runtime.h>
#include <cuda_bf16.h>
#include <math.h>

#define NN 50000
#define EE 800000
#define ET (EE + NN)
#define F1 128
#define C2 64
#define NEG 0.2f
#define MINIT -1e30f

#define SCAN_B 196                       // ceil(50000/256)

// ---------------- scratch ----------------------------------------------------
__device__ int    g_is64;
__device__ int    g_src [ET];
__device__ int    g_dst [ET];
__device__ int    g_row [NN + 1];
__device__ int    g_wpos[NN];
__device__ int    g_bsum[SCAN_B];
__device__ int    g_csrc[ET];

__device__ float  g_h1  [NN * F1];
__device__ float  g_h1e [NN * F1];
__device__ float4 g_as1 [NN];
__device__ float4 g_ad1 [NN];

__device__ float  g_h2  [NN * C2];
__device__ float  g_as2 [NN];
__device__ float  g_ad2 [NN];

__device__ __forceinline__ float lrelu(float v) { return v > 0.0f ? v : NEG * v; }

// ---------------- index dtype detection (parallel) ----------------------------
__global__ void detect_kernel(const void* __restrict__ ei) {
    int t = threadIdx.x;                      // 256 threads
    const unsigned long long* p = (const unsigned long long*)ei;
    int bad = (p[t] >= (unsigned long long)NN) ? 1 : 0;
    __shared__ int sbad;
    if (t == 0) sbad = 0;
    __syncthreads();
    if (__syncthreads_or(bad)) { if (t == 0) g_is64 = 0; }
    else                       { if (t == 0) g_is64 = 1; }
}

__global__ void zero_cnt_kernel() {
    int i = blockIdx.x * blockDim.x + threadIdx.x;
    if (i < NN) g_wpos[i] = 0;
}

__global__ void convert_hist_kernel(const void* __restrict__ ei) {
    int e = blockIdx.x * blockDim.x + threadIdx.x;
    if (e >= ET) return;
    int s, d;
    if (e >= EE) s = d = e - EE;
    else if (g_is64) {
        s = (int)((const long long*)ei)[e];
        d = (int)((const long long*)ei)[EE + e];
    } else {
        s = ((const int*)ei)[e];
        d = ((const int*)ei)[EE + e];
    }
    g_src[e] = s;
    g_dst[e] = d;
    atomicAdd(&g_wpos[d], 1);
}

// ---------------- hierarchical exclusive scan of g_wpos -> g_row -------------
__device__ __forceinline__ int block_excl_scan(int v, int t, int* total) {
    // 256-thread exclusive scan; returns exclusive prefix, *total = block sum
    __shared__ int wsum[8];
    int lane = t & 31, w = t >> 5;
    int inc = v;
#pragma unroll
    for (int o = 1; o < 32; o <<= 1) {
        int u = __shfl_up_sync(0xffffffffu, inc, o);
        if (lane >= o) inc += u;
    }
    if (lane == 31) wsum[w] = inc;
    __syncthreads();
    if (w == 0) {
        int ws = (lane < 8) ? wsum[lane] : 0;
#pragma unroll
        for (int o = 1; o < 8; o <<= 1) {
            int u = __shfl_up_sync(0xffffffffu, ws, o);
            if (lane >= o) ws += u;
        }
        if (lane < 8) wsum[lane] = ws;
    }
    __syncthreads();
    int base = (w > 0) ? wsum[w - 1] : 0;
    *total = wsum[7];
    return base + inc - v;
}

__global__ void scan1_kernel() {
    int t = threadIdx.x;
    int i = blockIdx.x * 256 + t;
    int v = (i < NN) ? g_wpos[i] : 0;
    int total;
    int ex = block_excl_scan(v, t, &total);
    if (i < NN) g_row[i] = ex;
    if (t == 0) g_bsum[blockIdx.x] = total;
}

__global__ void scan2_kernel() {        // 1 block, 256 threads
    int t = threadIdx.x;
    int v = (t < SCAN_B) ? g_bsum[t] : 0;
    int total;
    int ex = block_excl_scan(v, t, &total);
    if (t < SCAN_B) g_bsum[t] = ex;
}

__global__ void scan3_kernel() {
    int i = blockIdx.x * 256 + threadIdx.x;
    if (i < NN) {
        int r = g_row[i] + g_bsum[blockIdx.x];
        g_row[i] = r;
        g_wpos[i] = r;
    }
    if (i == 0) g_row[NN] = ET;
}

__global__ void scatter_kernel() {
    int e = blockIdx.x * blockDim.x + threadIdx.x;
    if (e >= ET) return;
    int d = g_dst[e];
    int p = atomicAdd(&g_wpos[d], 1);
    g_csrc[p] = g_src[e];
}

// ---------------- gemm1: h1 = x@W1 + alpha reductions (16 nodes/block) -------
__global__ void __launch_bounds__(128) gemm1_kernel(
        const float* __restrict__ x, const float* __restrict__ W,
        const float* __restrict__ as, const float* __restrict__ ad) {
    __shared__ float xs[16][128];
    int n0 = blockIdx.x * 16;
    int t = threadIdx.x;
    const float4* x4 = (const float4*)(x + n0 * 128);
    float4* xs4 = (float4*)xs;
#pragma unroll
    for (int r = 0; r < 4; r++) xs4[t + r * 128] = x4[t + r * 128];
    __syncthreads();
    int j = t;
    float acc[16];
#pragma unroll
    for (int n = 0; n < 16; n++) acc[n] = 0.0f;
#pragma unroll
    for (int k = 0; k < 128; k += 4) {
        float w0 = W[(k + 0) * 128 + j];
        float w1 = W[(k + 1) * 128 + j];
        float w2 = W[(k + 2) * 128 + j];
        float w3 = W[(k + 3) * 128 + j];
#pragma unroll
        for (int n = 0; n < 16; n++) {
            float4 xv = *(const float4*)&xs[n][k];
            acc[n] = fmaf(xv.x, w0, acc[n]);
            acc[n] = fmaf(xv.y, w1, acc[n]);
            acc[n] = fmaf(xv.z, w2, acc[n]);
            acc[n] = fmaf(xv.w, w3, acc[n]);
        }
    }
    float asj = as[j], adj = ad[j];
    int h = j >> 5;
#pragma unroll
    for (int n = 0; n < 16; n++) {
        g_h1[(n0 + n) * 128 + j] = acc[n];
        float vs = acc[n] * asj;
        float vd = acc[n] * adj;
#pragma unroll
        for (int o = 16; o; o >>= 1) {
            vs += __shfl_xor_sync(0xffffffffu, vs, o);
            vd += __shfl_xor_sync(0xffffffffu, vd, o);
        }
        if ((j & 31) == 0) {
            ((float*)&g_as1[n0 + n])[h] = vs;
            ((float*)&g_ad1[n0 + n])[h] = vd;
        }
    }
}

// ---------------- fused online-softmax aggregation, layer 1 -------------------
__global__ void __launch_bounds__(256) agg1_kernel(const float* __restrict__ b1) {
    int warp = threadIdx.x >> 5, lane = threadIdx.x & 31;
    int d = blockIdx.x * 8 + warp;
    int lo = g_row[d], hi = g_row[d + 1];
    int h = lane >> 3;
    float add = ((const float*)&g_ad1[d])[h];
    float m = MINIT, s = 0.0f;
    float4 acc = make_float4(0, 0, 0, 0);
    for (int i = lo; i < hi; i++) {
        int sc = g_csrc[i];
        float e = lrelu(((const float*)&g_as1[sc])[h] + add);
        float4 hv = *(const float4*)&g_h1[sc * 128 + lane * 4];
        float mn = fmaxf(m, e);
        float r = __expf(m - mn);
        float w = __expf(e - mn);
        s = s * r + w;
        acc.x = fmaf(acc.x, r, w * hv.x);
        acc.y = fmaf(acc.y, r, w * hv.y);
        acc.z = fmaf(acc.z, r, w * hv.z);
        acc.w = fmaf(acc.w, r, w * hv.w);
        m = mn;
    }
    float inv = 1.0f / (s + 1e-16f);
    int j = lane * 4;
    float4 bv = *(const float4*)&b1[j];
    float4 o;
    o.x = acc.x * inv + bv.x;
    o.y = acc.y * inv + bv.y;
    o.z = acc.z * inv + bv.z;
    o.w = acc.w * inv + bv.w;
    o.x = o.x > 0.0f ? o.x : expm1f(o.x);
    o.y = o.y > 0.0f ? o.y : expm1f(o.y);
    o.z = o.z > 0.0f ? o.z : expm1f(o.z);
    o.w = o.w > 0.0f ? o.w : expm1f(o.w);
    *(float4*)&g_h1e[d * 128 + j] = o;
}

// ---------------- gemm2 (16 nodes/block, 64 threads) --------------------------
__global__ void __launch_bounds__(64) gemm2_kernel(
        const float* __restrict__ W,
        const float* __restrict__ as, const float* __restrict__ ad) {
    __shared__ float xs[16][128];
    __shared__ float ps[16][2], pd[16][2];
    int n0 = blockIdx.x * 16;
    int t = threadIdx.x;
    const float4* x4 = (const float4*)(g_h1e + n0 * 128);
    float4* xs4 = (float4*)xs;
#pragma unroll
    for (int r = 0; r < 8; r++) xs4[t + r * 64] = x4[t + r * 64];
    __syncthreads();
    int j = t;
    float acc[16];
#pragma unroll
    for (int n = 0; n < 16; n++) acc[n] = 0.0f;
#pragma unroll
    for (int k = 0; k < 128; k += 4) {
        float w0 = W[(k + 0) * 64 + j];
        float w1 = W[(k + 1) * 64 + j];
        float w2 = W[(k + 2) * 64 + j];
        float w3 = W[(k + 3) * 64 + j];
#pragma unroll
        for (int n = 0; n < 16; n++) {
            float4 xv = *(const float4*)&xs[n][k];
            acc[n] = fmaf(xv.x, w0, acc[n]);
            acc[n] = fmaf(xv.y, w1, acc[n]);
            acc[n] = fmaf(xv.z, w2, acc[n]);
            acc[n] = fmaf(xv.w, w3, acc[n]);
        }
    }
    float asj = as[j], adj = ad[j];
    int w = t >> 5;
#pragma unroll
    for (int n = 0; n < 16; n++) {
        g_h2[(n0 + n) * 64 + j] = acc[n];
        float vs = acc[n] * asj;
        float vd = acc[n] * adj;
#pragma unroll
        for (int o = 16; o; o >>= 1) {
            vs += __shfl_xor_sync(0xffffffffu, vs, o);
            vd += __shfl_xor_sync(0xffffffffu, vd, o);
        }
        if ((t & 31) == 0) { ps[n][w] = vs; pd[n][w] = vd; }
    }
    __syncthreads();
    if (t < 16) {
        g_as2[n0 + t] = ps[t][0] + ps[t][1];
        g_ad2[n0 + t] = pd[t][0] + pd[t][1];
    }
}

// ---------------- fused online-softmax aggregation, layer 2 -------------------
__global__ void __launch_bounds__(256) agg2_kernel(
        float* __restrict__ out, const float* __restrict__ b2) {
    int warp = threadIdx.x >> 5, lane = threadIdx.x & 31;
    int d = blockIdx.x * 8 + warp;
    int lo = g_row[d], hi = g_row[d + 1];
    float add = g_ad2[d];
    float m = MINIT, s = 0.0f;
    float2 acc = make_float2(0, 0);
    for (int i = lo; i < hi; i++) {
        int sc = g_csrc[i];
        float e = lrelu(g_as2[sc] + add);
        float2 hv = *(const float2*)&g_h2[sc * 64 + lane * 2];
        float mn = fmaxf(m, e);
        float r = __expf(m - mn);
        float w = __expf(e - mn);
        s = s * r + w;
        acc.x = fmaf(acc.x, r, w * hv.x);
        acc.y = fmaf(acc.y, r, w * hv.y);
        m = mn;
    }
    float inv = 1.0f / (s + 1e-16f);
    int j = lane * 2;
    float2 o;
    o.x = acc.x * inv + b2[j];
    o.y = acc.y * inv + b2[j + 1];
    *(float2*)&out[d * 64 + j] = o;
}

// ---------------- launch -------------------------------------------------------
extern "C" void kernel_launch(void* const* d_in, const int* in_sizes, int n_in,
                              void* d_out, int out_size) {
    const float* x   = (const float*)d_in[0];
    const void*  ei  = d_in[1];
    const float* W1  = (const float*)d_in[2];
    const float* as1 = (const float*)d_in[3];
    const float* ad1 = (const float*)d_in[4];
    const float* b1  = (const float*)d_in[5];
    const float* W2  = (const float*)d_in[6];
    const float* as2 = (const float*)d_in[7];
    const float* ad2 = (const float*)d_in[8];
    const float* b2  = (const float*)d_in[9];
    float*       out = (float*)d_out;

    const int TB = 256;
    auto nb = [](long long n, int tb) { return (int)((n + tb - 1) / tb); };

    detect_kernel<<<1, 256>>>(ei);
    zero_cnt_kernel<<<nb(NN, TB), TB>>>();
    convert_hist_kernel<<<nb(ET, TB), TB>>>(ei);
    scan1_kernel<<<SCAN_B, 256>>>();
    scan2_kernel<<<1, 256>>>();
    scan3_kernel<<<SCAN_B, 256>>>();
    scatter_kernel<<<nb(ET, TB), TB>>>();

    gemm1_kernel<<<NN / 16, 128>>>(x, W1, as1, ad1);
    agg1_kernel<<<NN / 8, 256>>>(b1);

    gemm2_kernel<<<NN / 16, 64>>>(W2, as2, ad2);
    agg2_kernel<<<NN / 8, 256>>>(out, b2);
}

// round 6
// speedup vs baseline: 3.2126x; 1.0603x over previous
#include <cuda_runtime.h>
#include <cuda_bf16.h>
#include <math.h>

#define NN 50000
#define EE 800000
#define ET (EE + NN)
#define F1 128
#define C2 64
#define NEG 0.2f

#define SCAN_B 196                       // ceil(50000/256)

// ---------------- scratch ----------------------------------------------------
__device__ int    g_is64;
__device__ int    g_src [ET];
__device__ int    g_dst [ET];
__device__ int    g_row [NN + 1];
__device__ int    g_wpos[NN];
__device__ int    g_bsum[SCAN_B];
__device__ int    g_csrc[ET];

__device__ float  g_h1  [NN * F1];
__device__ float  g_h1e [NN * F1];
__device__ float4 g_as1 [NN];
__device__ float4 g_ad1 [NN];

__device__ float  g_h2  [NN * C2];
__device__ float  g_as2 [NN];
__device__ float  g_ad2 [NN];

__device__ __forceinline__ float lrelu(float v) { return v > 0.0f ? v : NEG * v; }

// ---------------- zero counters + dtype detect (block 0) ----------------------
__global__ void zero_detect_kernel(const void* __restrict__ ei) {
    int i = blockIdx.x * blockDim.x + threadIdx.x;
    if (i < NN) g_wpos[i] = 0;
    if (blockIdx.x == 0) {
        const unsigned long long* p = (const unsigned long long*)ei;
        int bad = (p[threadIdx.x] >= (unsigned long long)NN) ? 1 : 0;
        int anybad = __syncthreads_or(bad);
        if (threadIdx.x == 0) g_is64 = anybad ? 0 : 1;
    }
}

__global__ void convert_hist_kernel(const void* __restrict__ ei) {
    int e = blockIdx.x * blockDim.x + threadIdx.x;
    if (e >= ET) return;
    int s, d;
    if (e >= EE) s = d = e - EE;
    else if (g_is64) {
        s = (int)((const long long*)ei)[e];
        d = (int)((const long long*)ei)[EE + e];
    } else {
        s = ((const int*)ei)[e];
        d = ((const int*)ei)[EE + e];
    }
    g_src[e] = s;
    g_dst[e] = d;
    atomicAdd(&g_wpos[d], 1);
}

// ---------------- scan: block-local then per-block global fixup ---------------
__device__ __forceinline__ int block_excl_scan(int v, int t, int* total) {
    __shared__ int wsum[8];
    int lane = t & 31, w = t >> 5;
    int inc = v;
#pragma unroll
    for (int o = 1; o < 32; o <<= 1) {
        int u = __shfl_up_sync(0xffffffffu, inc, o);
        if (lane >= o) inc += u;
    }
    if (lane == 31) wsum[w] = inc;
    __syncthreads();
    if (w == 0) {
        int ws = (lane < 8) ? wsum[lane] : 0;
#pragma unroll
        for (int o = 1; o < 8; o <<= 1) {
            int u = __shfl_up_sync(0xffffffffu, ws, o);
            if (lane >= o) ws += u;
        }
        if (lane < 8) wsum[lane] = ws;
    }
    __syncthreads();
    int base = (w > 0) ? wsum[w - 1] : 0;
    *total = wsum[7];
    return base + inc - v;
}

__global__ void scan1_kernel() {
    int t = threadIdx.x;
    int i = blockIdx.x * 256 + t;
    int v = (i < NN) ? g_wpos[i] : 0;
    int total;
    int ex = block_excl_scan(v, t, &total);
    if (i < NN) g_row[i] = ex;
    if (t == 0) g_bsum[blockIdx.x] = total;
}

// each block computes its own exclusive prefix of the 196 block sums
__global__ void scan3_kernel() {
    __shared__ int ws[8];
    __shared__ int sbase;
    int t = threadIdx.x, b = blockIdx.x;
    int lane = t & 31, w = t >> 5;
    int v = (t < SCAN_B && t < b) ? g_bsum[t] : 0;
#pragma unroll
    for (int o = 16; o; o >>= 1) v += __shfl_xor_sync(0xffffffffu, v, o);
    if (lane == 0) ws[w] = v;
    __syncthreads();
    if (t == 0) {
        int tot = 0;
#pragma unroll
        for (int k = 0; k < 8; k++) tot += ws[k];
        sbase = tot;
    }
    __syncthreads();
    int i = b * 256 + t;
    if (i < NN) {
        int r = g_row[i] + sbase;
        g_row[i] = r;
        g_wpos[i] = r;
    }
    if (i == 0) g_row[NN] = ET;
}

__global__ void scatter_kernel() {
    int e = blockIdx.x * blockDim.x + threadIdx.x;
    if (e >= ET) return;
    int d = g_dst[e];
    int p = atomicAdd(&g_wpos[d], 1);
    g_csrc[p] = g_src[e];
}

// ---------------- gemm1: h1 = x@W1 + alpha reductions (16 nodes/block) -------
__global__ void __launch_bounds__(128) gemm1_kernel(
        const float* __restrict__ x, const float* __restrict__ W,
        const float* __restrict__ as, const float* __restrict__ ad) {
    __shared__ float xs[16][128];
    int n0 = blockIdx.x * 16;
    int t = threadIdx.x;
    const float4* x4 = (const float4*)(x + n0 * 128);
    float4* xs4 = (float4*)xs;
#pragma unroll
    for (int r = 0; r < 4; r++) xs4[t + r * 128] = x4[t + r * 128];
    __syncthreads();
    int j = t;
    float acc[16];
#pragma unroll
    for (int n = 0; n < 16; n++) acc[n] = 0.0f;
#pragma unroll
    for (int k = 0; k < 128; k += 4) {
        float w0 = W[(k + 0) * 128 + j];
        float w1 = W[(k + 1) * 128 + j];
        float w2 = W[(k + 2) * 128 + j];
        float w3 = W[(k + 3) * 128 + j];
#pragma unroll
        for (int n = 0; n < 16; n++) {
            float4 xv = *(const float4*)&xs[n][k];
            acc[n] = fmaf(xv.x, w0, acc[n]);
            acc[n] = fmaf(xv.y, w1, acc[n]);
            acc[n] = fmaf(xv.z, w2, acc[n]);
            acc[n] = fmaf(xv.w, w3, acc[n]);
        }
    }
    float asj = as[j], adj = ad[j];
    int h = j >> 5;
#pragma unroll
    for (int n = 0; n < 16; n++) {
        g_h1[(n0 + n) * 128 + j] = acc[n];
        float vs = acc[n] * asj;
        float vd = acc[n] * adj;
#pragma unroll
        for (int o = 16; o; o >>= 1) {
            vs += __shfl_xor_sync(0xffffffffu, vs, o);
            vd += __shfl_xor_sync(0xffffffffu, vd, o);
        }
        if ((j & 31) == 0) {
            ((float*)&g_as1[n0 + n])[h] = vs;
            ((float*)&g_ad1[n0 + n])[h] = vd;
        }
    }
}

// ---------------- fused softmax aggregation (max-free), layer 1 --------------
// warp per dst node; lane handles 4 channels; 4-edge unroll for MLP.
__global__ void __launch_bounds__(256) agg1_kernel(const float* __restrict__ b1) {
    int warp = threadIdx.x >> 5, lane = threadIdx.x & 31;
    int d = blockIdx.x * 8 + warp;
    int lo = g_row[d], hi = g_row[d + 1];
    int h = lane >> 3;
    float add = ((const float*)&g_ad1[d])[h];
    float s = 0.0f;
    float4 acc = make_float4(0, 0, 0, 0);
    int co = lane * 4;
    int i = lo;
    for (; i + 4 <= hi; i += 4) {
        int s0 = g_csrc[i], s1 = g_csrc[i + 1], s2 = g_csrc[i + 2], s3 = g_csrc[i + 3];
        float a0 = ((const float*)&g_as1[s0])[h];
        float a1 = ((const float*)&g_as1[s1])[h];
        float a2 = ((const float*)&g_as1[s2])[h];
        float a3 = ((const float*)&g_as1[s3])[h];
        float4 h0 = *(const float4*)&g_h1[s0 * 128 + co];
        float4 h1 = *(const float4*)&g_h1[s1 * 128 + co];
        float4 h2 = *(const float4*)&g_h1[s2 * 128 + co];
        float4 h3 = *(const float4*)&g_h1[s3 * 128 + co];
        float w0 = __expf(lrelu(a0 + add));
        float w1 = __expf(lrelu(a1 + add));
        float w2 = __expf(lrelu(a2 + add));
        float w3 = __expf(lrelu(a3 + add));
        s += (w0 + w1) + (w2 + w3);
        acc.x = fmaf(w0, h0.x, acc.x); acc.y = fmaf(w0, h0.y, acc.y);
        acc.z = fmaf(w0, h0.z, acc.z); acc.w = fmaf(w0, h0.w, acc.w);
        acc.x = fmaf(w1, h1.x, acc.x); acc.y = fmaf(w1, h1.y, acc.y);
        acc.z = fmaf(w1, h1.z, acc.z); acc.w = fmaf(w1, h1.w, acc.w);
        acc.x = fmaf(w2, h2.x, acc.x); acc.y = fmaf(w2, h2.y, acc.y);
        acc.z = fmaf(w2, h2.z, acc.z); acc.w = fmaf(w2, h2.w, acc.w);
        acc.x = fmaf(w3, h3.x, acc.x); acc.y = fmaf(w3, h3.y, acc.y);
        acc.z = fmaf(w3, h3.z, acc.z); acc.w = fmaf(w3, h3.w, acc.w);
    }
    for (; i < hi; i++) {
        int sc = g_csrc[i];
        float w = __expf(lrelu(((const float*)&g_as1[sc])[h] + add));
        float4 hv = *(const float4*)&g_h1[sc * 128 + co];
        s += w;
        acc.x = fmaf(w, hv.x, acc.x); acc.y = fmaf(w, hv.y, acc.y);
        acc.z = fmaf(w, hv.z, acc.z); acc.w = fmaf(w, hv.w, acc.w);
    }
    float inv = 1.0f / (s + 1e-16f);
    float4 bv = *(const float4*)&b1[co];
    float4 o;
    o.x = acc.x * inv + bv.x;
    o.y = acc.y * inv + bv.y;
    o.z = acc.z * inv + bv.z;
    o.w = acc.w * inv + bv.w;
    o.x = o.x > 0.0f ? o.x : expm1f(o.x);
    o.y = o.y > 0.0f ? o.y : expm1f(o.y);
    o.z = o.z > 0.0f ? o.z : expm1f(o.z);
    o.w = o.w > 0.0f ? o.w : expm1f(o.w);
    *(float4*)&g_h1e[d * 128 + co] = o;
}

// ---------------- gemm2 (16 nodes/block, 64 threads) --------------------------
__global__ void __launch_bounds__(64) gemm2_kernel(
        const float* __restrict__ W,
        const float* __restrict__ as, const float* __restrict__ ad) {
    __shared__ float xs[16][128];
    __shared__ float ps[16][2], pd[16][2];
    int n0 = blockIdx.x * 16;
    int t = threadIdx.x;
    const float4* x4 = (const float4*)(g_h1e + n0 * 128);
    float4* xs4 = (float4*)xs;
#pragma unroll
    for (int r = 0; r < 8; r++) xs4[t + r * 64] = x4[t + r * 64];
    __syncthreads();
    int j = t;
    float acc[16];
#pragma unroll
    for (int n = 0; n < 16; n++) acc[n] = 0.0f;
#pragma unroll
    for (int k = 0; k < 128; k += 4) {
        float w0 = W[(k + 0) * 64 + j];
        float w1 = W[(k + 1) * 64 + j];
        float w2 = W[(k + 2) * 64 + j];
        float w3 = W[(k + 3) * 64 + j];
#pragma unroll
        for (int n = 0; n < 16; n++) {
            float4 xv = *(const float4*)&xs[n][k];
            acc[n] = fmaf(xv.x, w0, acc[n]);
            acc[n] = fmaf(xv.y, w1, acc[n]);
            acc[n] = fmaf(xv.z, w2, acc[n]);
            acc[n] = fmaf(xv.w, w3, acc[n]);
        }
    }
    float asj = as[j], adj = ad[j];
    int w = t >> 5;
#pragma unroll
    for (int n = 0; n < 16; n++) {
        g_h2[(n0 + n) * 64 + j] = acc[n];
        float vs = acc[n] * asj;
        float vd = acc[n] * adj;
#pragma unroll
        for (int o = 16; o; o >>= 1) {
            vs += __shfl_xor_sync(0xffffffffu, vs, o);
            vd += __shfl_xor_sync(0xffffffffu, vd, o);
        }
        if ((t & 31) == 0) { ps[n][w] = vs; pd[n][w] = vd; }
    }
    __syncthreads();
    if (t < 16) {
        g_as2[n0 + t] = ps[t][0] + ps[t][1];
        g_ad2[n0 + t] = pd[t][0] + pd[t][1];
    }
}

// ---------------- fused softmax aggregation (max-free), layer 2 --------------
__global__ void __launch_bounds__(256) agg2_kernel(
        float* __restrict__ out, const float* __restrict__ b2) {
    int warp = threadIdx.x >> 5, lane = threadIdx.x & 31;
    int d = blockIdx.x * 8 + warp;
    int lo = g_row[d], hi = g_row[d + 1];
    float add = g_ad2[d];
    float s = 0.0f;
    float2 acc = make_float2(0, 0);
    int co = lane * 2;
    int i = lo;
    for (; i + 4 <= hi; i += 4) {
        int s0 = g_csrc[i], s1 = g_csrc[i + 1], s2 = g_csrc[i + 2], s3 = g_csrc[i + 3];
        float a0 = g_as2[s0], a1 = g_as2[s1], a2 = g_as2[s2], a3 = g_as2[s3];
        float2 h0 = *(const float2*)&g_h2[s0 * 64 + co];
        float2 h1 = *(const float2*)&g_h2[s1 * 64 + co];
        float2 h2 = *(const float2*)&g_h2[s2 * 64 + co];
        float2 h3 = *(const float2*)&g_h2[s3 * 64 + co];
        float w0 = __expf(lrelu(a0 + add));
        float w1 = __expf(lrelu(a1 + add));
        float w2 = __expf(lrelu(a2 + add));
        float w3 = __expf(lrelu(a3 + add));
        s += (w0 + w1) + (w2 + w3);
        acc.x = fmaf(w0, h0.x, acc.x); acc.y = fmaf(w0, h0.y, acc.y);
        acc.x = fmaf(w1, h1.x, acc.x); acc.y = fmaf(w1, h1.y, acc.y);
        acc.x = fmaf(w2, h2.x, acc.x); acc.y = fmaf(w2, h2.y, acc.y);
        acc.x = fmaf(w3, h3.x, acc.x); acc.y = fmaf(w3, h3.y, acc.y);
    }
    for (; i < hi; i++) {
        int sc = g_csrc[i];
        float w = __expf(lrelu(g_as2[sc] + add));
        float2 hv = *(const float2*)&g_h2[sc * 64 + co];
        s += w;
        acc.x = fmaf(w, hv.x, acc.x);
        acc.y = fmaf(w, hv.y, acc.y);
    }
    float inv = 1.0f / (s + 1e-16f);
    float2 o;
    o.x = acc.x * inv + b2[co];
    o.y = acc.y * inv + b2[co + 1];
    *(float2*)&out[d * 64 + co] = o;
}

// ---------------- launch -------------------------------------------------------
extern "C" void kernel_launch(void* const* d_in, const int* in_sizes, int n_in,
                              void* d_out, int out_size) {
    const float* x   = (const float*)d_in[0];
    const void*  ei  = d_in[1];
    const float* W1  = (const float*)d_in[2];
    const float* as1 = (const float*)d_in[3];
    const float* ad1 = (const float*)d_in[4];
    const float* b1  = (const float*)d_in[5];
    const float* W2  = (const float*)d_in[6];
    const float* as2 = (const float*)d_in[7];
    const float* ad2 = (const float*)d_in[8];
    const float* b2  = (const float*)d_in[9];
    float*       out = (float*)d_out;

    const int TB = 256;
    auto nb = [](long long n, int tb) { return (int)((n + tb - 1) / tb); };

    zero_detect_kernel<<<SCAN_B, 256>>>(ei);
    convert_hist_kernel<<<nb(ET, TB), TB>>>(ei);
    scan1_kernel<<<SCAN_B, 256>>>();
    scan3_kernel<<<SCAN_B, 256>>>();
    scatter_kernel<<<nb(ET, TB), TB>>>();

    gemm1_kernel<<<NN / 16, 128>>>(x, W1, as1, ad1);
    agg1_kernel<<<NN / 8, 256>>>(b1);

    gemm2_kernel<<<NN / 16, 64>>>(W2, as2, ad2);
    agg2_kernel<<<NN / 8, 256>>>(out, b2);
}